// round 8
// baseline (speedup 1.0000x reference)
#include <cuda_runtime.h>
#include <cuda_bf16.h>
#include <cstdint>
#include <math.h>

#define D 128
#define NMAX 100000
#define NPAD_MAX 100096

// ---- scratch (static device globals; no runtime allocation) ----
static __device__ float g_agg[(size_t)NMAX * D];                // scatter-sum of gathered rows
static __device__ __nv_bfloat16 g_Xhi[(size_t)NPAD_MAX * 256];  // X hi split
static __device__ __nv_bfloat16 g_Xlo[(size_t)NPAD_MAX * 256];  // X lo split
static __device__ __nv_bfloat16 g_B[512 * 768];                 // gate-interleaved rows d*4+gate
static __device__ float g_bias[512];                            // br, bz, bxn, bhh_n
static __device__ float g_ss[NPAD_MAX];                         // per-node sum of squares

// ============================ PTX helpers (plain sm_103) ============================
__device__ __forceinline__ uint32_t smem_u32(const void* p) {
    uint32_t a;
    asm("{ .reg .u64 t; cvta.to.shared.u64 t, %1; cvt.u32.u64 %0, t; }" : "=r"(a) : "l"(p));
    return a;
}
__device__ __forceinline__ void cp_async16(uint32_t dst, const void* src) {
    asm volatile("cp.async.cg.shared.global [%0], [%1], 16;" :: "r"(dst), "l"(src));
}
__device__ __forceinline__ void ldm_x4(uint32_t* r, uint32_t addr) {
    asm volatile("ldmatrix.sync.aligned.m8n8.x4.shared.b16 {%0,%1,%2,%3}, [%4];"
                 : "=r"(r[0]), "=r"(r[1]), "=r"(r[2]), "=r"(r[3]) : "r"(addr));
}
__device__ __forceinline__ void mma_bf16(float* c, const uint32_t* a, uint32_t b0, uint32_t b1) {
    asm volatile(
        "mma.sync.aligned.m16n8k16.row.col.f32.bf16.bf16.f32 "
        "{%0,%1,%2,%3}, {%4,%5,%6,%7}, {%8,%9}, {%0,%1,%2,%3};"
        : "+f"(c[0]), "+f"(c[1]), "+f"(c[2]), "+f"(c[3])
        : "r"(a[0]), "r"(a[1]), "r"(a[2]), "r"(a[3]), "r"(b0), "r"(b1));
}
__device__ __forceinline__ float sigmoidf_(float x) { return 1.f / (1.f + expf(-x)); }

// ============================ prep: folded B (bf16 hi/lo, gate-interleaved) + biases =====
// Logical row n = gate*128 + d; stored at row' = d*4 + gate.
__global__ void prep_kernel(const float* __restrict__ W, const float* __restrict__ w_ih,
                            const float* __restrict__ w_hh, const float* __restrict__ b_ih,
                            const float* __restrict__ b_hh) {
    int n = blockIdx.x;
    int k = threadIdx.x;
    if (n == 512) {
        if (k < 128) {
            g_bias[k]       = b_ih[k] + b_hh[k];
            g_bias[128 + k] = b_ih[128 + k] + b_hh[128 + k];
            g_bias[256 + k] = b_ih[256 + k];
            g_bias[384 + k] = b_hh[256 + k];
        }
        return;
    }
    float v;
    if (k < 128) {
        if (n < 384) {
            float acc = 0.f;
            for (int j = 0; j < 128; j++) acc = fmaf(W[k * 128 + j], w_ih[n * 256 + j], acc);
            v = acc;
        } else v = 0.f;
    } else {
        if (n < 256)      v = w_ih[n * 256 + k] + w_hh[n * 128 + (k - 128)];
        else if (n < 384) v = w_ih[n * 256 + k];
        else              v = w_hh[(n - 128) * 128 + (k - 128)];
    }
    __nv_bfloat16 hi = __float2bfloat16_rn(v);
    __nv_bfloat16 lo = __float2bfloat16_rn(v - __bfloat162float(hi));
    int rp = (n & 127) * 4 + (n >> 7);   // gate-interleaved row
    g_B[rp * 768 + k] = hi;
    g_B[rp * 768 + 256 + k] = hi;
    g_B[rp * 768 + 512 + k] = lo;
}

// ============================ zero / scatter ============================
__global__ void zero_kernel(int N, int npad) {
    size_t total = (size_t)N * 32;
    float4* p = reinterpret_cast<float4*>(g_agg);
    for (size_t i = blockIdx.x * (size_t)blockDim.x + threadIdx.x; i < total;
         i += (size_t)gridDim.x * blockDim.x)
        p[i] = make_float4(0.f, 0.f, 0.f, 0.f);
    for (int i = blockIdx.x * blockDim.x + threadIdx.x; i < npad;
         i += gridDim.x * blockDim.x)
        g_ss[i] = 0.f;
}

// 4 edges per warp; reads ent rows directly via node_id indirection.
__global__ __launch_bounds__(256) void scatter_kernel(const float* __restrict__ ent,
                                                      const int* __restrict__ node_id,
                                                      const int* __restrict__ esrc,
                                                      const int* __restrict__ edst, int E) {
    int warp = (int)((blockIdx.x * (size_t)blockDim.x + threadIdx.x) >> 5);
    int lane = threadIdx.x & 31;
    int e0 = warp * 4;
    if (e0 >= E) return;
    int dst[4], row[4];
    #pragma unroll
    for (int j = 0; j < 4; j++) {
        if (e0 + j < E) {
            int s = __ldg(esrc + e0 + j);
            dst[j] = __ldg(edst + e0 + j);
            row[j] = __ldg(node_id + s);
        } else {
            dst[j] = -1; row[j] = 0;
        }
    }
    float4 v[4];
    #pragma unroll
    for (int j = 0; j < 4; j++)
        v[j] = __ldg(reinterpret_cast<const float4*>(ent) + (size_t)row[j] * 32 + lane);
    #pragma unroll
    for (int j = 0; j < 4; j++)
        if (dst[j] >= 0)
            atomicAdd(reinterpret_cast<float4*>(g_agg) + (size_t)dst[j] * 32 + lane, v[j]);
}

// ============================ build X (hi/lo bf16 split) ============================
__global__ __launch_bounds__(256) void build_x_kernel(const float* __restrict__ erb,
                                                      const float* __restrict__ onorm,
                                                      int N, int npad) {
    int i = blockIdx.x * blockDim.x + threadIdx.x;
    int node = i >> 5, lane = i & 31;
    if (node >= npad) return;
    float x[8];
    if (node < N) {
        float sc = __ldg(onorm + node);
        float4 a = __ldg(reinterpret_cast<const float4*>(g_agg) + (size_t)node * 32 + lane);
        float4 e = __ldg(reinterpret_cast<const float4*>(erb) + (size_t)node * 32 + lane);
        x[0] = a.x * sc; x[1] = a.y * sc; x[2] = a.z * sc; x[3] = a.w * sc;
        x[4] = e.x; x[5] = e.y; x[6] = e.z; x[7] = e.w;
    } else {
        #pragma unroll
        for (int q = 0; q < 8; q++) x[q] = 0.f;
    }
    unsigned short hs[8], ls[8];
    #pragma unroll
    for (int q = 0; q < 8; q++) {
        __nv_bfloat16 hb = __float2bfloat16_rn(x[q]);
        __nv_bfloat16 lb = __float2bfloat16_rn(x[q] - __bfloat162float(hb));
        hs[q] = *reinterpret_cast<unsigned short*>(&hb);
        ls[q] = *reinterpret_cast<unsigned short*>(&lb);
    }
    uint2* dhi0 = reinterpret_cast<uint2*>(g_Xhi + (size_t)node * 256 + lane * 4);
    uint2* dhi1 = reinterpret_cast<uint2*>(g_Xhi + (size_t)node * 256 + 128 + lane * 4);
    uint2* dlo0 = reinterpret_cast<uint2*>(g_Xlo + (size_t)node * 256 + lane * 4);
    uint2* dlo1 = reinterpret_cast<uint2*>(g_Xlo + (size_t)node * 256 + 128 + lane * 4);
    *dhi0 = make_uint2((uint32_t)hs[0] | ((uint32_t)hs[1] << 16), (uint32_t)hs[2] | ((uint32_t)hs[3] << 16));
    *dhi1 = make_uint2((uint32_t)hs[4] | ((uint32_t)hs[5] << 16), (uint32_t)hs[6] | ((uint32_t)hs[7] << 16));
    *dlo0 = make_uint2((uint32_t)ls[0] | ((uint32_t)ls[1] << 16), (uint32_t)ls[2] | ((uint32_t)ls[3] << 16));
    *dlo1 = make_uint2((uint32_t)ls[4] | ((uint32_t)ls[5] << 16), (uint32_t)ls[6] | ((uint32_t)ls[7] << 16));
}

// ============================ fused GEMM + GRU epilogue ============================
// C-block = 128 nodes x 128 interleaved cols = dims [32*by, 32*by+32) x 4 gates.
// After the k-loop: shfl gate pairs, fp32 gate math (identical to old epilogue),
// stage h in smem, coalesced store to out, per-node sumsq atomics into g_ss.
#define STAGE_BYTES 32768
#define GEMM_SMEM (3 * STAGE_BYTES)

__global__ __launch_bounds__(256, 2) void gemm_kernel(const float* __restrict__ erb,
                                                      float* __restrict__ out, int n_nodes) {
    extern __shared__ char smc[];
    uint32_t sbase = smem_u32(smc);
    int tid = threadIdx.x, lane = tid & 31, w = tid >> 5;
    int n0 = blockIdx.x * 128;
    int d0 = blockIdx.y * 128;          // interleaved-col block
    int dblk = blockIdx.y * 32;         // dim block
    int wm = w & 3, wn = w >> 2;
    int m0 = wm * 32, nw0 = wn * 64;

    float acc[2][8][4];
    #pragma unroll
    for (int a = 0; a < 2; a++)
        #pragma unroll
        for (int b = 0; b < 8; b++)
            #pragma unroll
            for (int c = 0; c < 4; c++) acc[a][b][c] = 0.f;

    auto load_chunk = [&](int c, int st) {
        const __nv_bfloat16* X = (c >= 4 && c < 8) ? g_Xlo : g_Xhi;
        const __nv_bfloat16* Asrc = X + (size_t)n0 * 256 + (c & 3) * 64;
        const __nv_bfloat16* Bsrc = g_B + (size_t)d0 * 768 + c * 64;
        uint32_t abase = sbase + st * STAGE_BYTES;
        uint32_t bbase = abase + 16384;
        #pragma unroll
        for (int i = 0; i < 4; i++) {
            int e = i * 256 + tid;
            int row = e >> 3, ch = e & 7;
            cp_async16(abase + (row * 8 + (ch ^ (row & 7))) * 16,
                       Asrc + (size_t)row * 256 + ch * 8);
        }
        #pragma unroll
        for (int i = 0; i < 4; i++) {
            int e = i * 256 + tid;
            int row = e >> 3, ch = e & 7;
            cp_async16(bbase + (row * 8 + (ch ^ (row & 7))) * 16,
                       Bsrc + (size_t)row * 768 + ch * 8);
        }
        asm volatile("cp.async.commit_group;" ::: "memory");
    };

    load_chunk(0, 0);
    load_chunk(1, 1);

    for (int i = 0; i < 12; i++) {
        int st = i % 3;
        if (i < 11) asm volatile("cp.async.wait_group 1;" ::: "memory");
        else        asm volatile("cp.async.wait_group 0;" ::: "memory");
        __syncthreads();
        if (i + 2 < 12) load_chunk(i + 2, (i + 2) % 3);
        uint32_t abase = sbase + st * STAGE_BYTES;
        uint32_t bbase = abase + 16384;
        #pragma unroll
        for (int k16 = 0; k16 < 4; k16++) {
            uint32_t af[2][4], bf[4][4];
            #pragma unroll
            for (int mi = 0; mi < 2; mi++) {
                int row = m0 + mi * 16 + (lane & 15);
                int ch = k16 * 2 + (lane >> 4);
                ldm_x4(af[mi], abase + (row * 8 + (ch ^ (row & 7))) * 16);
            }
            #pragma unroll
            for (int j = 0; j < 4; j++) {
                int row = nw0 + j * 16 + (lane & 15);
                int ch = k16 * 2 + (lane >> 4);
                ldm_x4(bf[j], bbase + (row * 8 + (ch ^ (row & 7))) * 16);
            }
            #pragma unroll
            for (int mi = 0; mi < 2; mi++)
                #pragma unroll
                for (int j = 0; j < 4; j++) {
                    mma_bf16(acc[mi][2 * j],     af[mi], bf[j][0], bf[j][2]);
                    mma_bf16(acc[mi][2 * j + 1], af[mi], bf[j][1], bf[j][3]);
                }
        }
    }
    __syncthreads();   // all mma reads of smem done; reuse buffers for epilogue

    // ---- fused epilogue ----
    float* hstage = reinterpret_cast<float*>(smc);      // [128][33]
    float* estage = hstage + 128 * 33;                  // [128][33]
    float* ssrow  = estage + 128 * 33;                  // [128]
    for (int i = tid; i < 128 * 32; i += 256) {
        int rl = i >> 5, dl = i & 31;
        int node = n0 + rl;
        estage[rl * 33 + dl] = (node < n_nodes)
            ? __ldg(erb + (size_t)node * 128 + dblk + dl) : 0.f;
    }
    if (tid < 128) ssrow[tid] = 0.f;
    __syncthreads();

    int tr = lane >> 2;
    float ssp[4] = {0.f, 0.f, 0.f, 0.f};
    #pragma unroll
    for (int mi = 0; mi < 2; mi++) {
        #pragma unroll
        for (int j = 0; j < 8; j++) {
            float* cp = acc[mi][j];
            float p0 = __shfl_xor_sync(0xFFFFFFFFu, cp[0], 1);
            float p1 = __shfl_xor_sync(0xFFFFFFFFu, cp[1], 1);
            float p2 = __shfl_xor_sync(0xFFFFFFFFu, cp[2], 1);
            float p3 = __shfl_xor_sync(0xFFFFFFFFu, cp[3], 1);
            if (!(lane & 1)) {
                // even lane holds (r,z); partner delivered (xn,hn) for same dim
                int dl = (nw0 >> 2) + 2 * j + ((lane >> 1) & 1);
                int d  = dblk + dl;
                float br = __ldg(g_bias + d),       bz = __ldg(g_bias + 128 + d);
                float bn = __ldg(g_bias + 256 + d), bh = __ldg(g_bias + 384 + d);
                int r0 = m0 + mi * 16 + tr;
                {
                    float r_ = sigmoidf_(cp[0] + br);
                    float z_ = sigmoidf_(cp[1] + bz);
                    float nn = tanhf(p0 + bn + r_ * (p1 + bh));
                    float h = fmaxf((1.f - z_) * nn + z_ * estage[r0 * 33 + dl], 0.f);
                    hstage[r0 * 33 + dl] = h;
                    ssp[mi * 2 + 0] += h * h;
                }
                int r1 = r0 + 8;
                {
                    float r_ = sigmoidf_(cp[2] + br);
                    float z_ = sigmoidf_(cp[3] + bz);
                    float nn = tanhf(p2 + bn + r_ * (p3 + bh));
                    float h = fmaxf((1.f - z_) * nn + z_ * estage[r1 * 33 + dl], 0.f);
                    hstage[r1 * 33 + dl] = h;
                    ssp[mi * 2 + 1] += h * h;
                }
            }
        }
    }
    if (!(lane & 1)) {
        atomicAdd(&ssrow[m0 + tr],       ssp[0]);
        atomicAdd(&ssrow[m0 + tr + 8],   ssp[1]);
        atomicAdd(&ssrow[m0 + 16 + tr],  ssp[2]);
        atomicAdd(&ssrow[m0 + 24 + tr],  ssp[3]);
    }
    __syncthreads();
    if (tid < 128) {
        int node = n0 + tid;
        if (node < n_nodes) atomicAdd(&g_ss[node], ssrow[tid]);
    }
    for (int i = tid; i < 128 * 32; i += 256) {
        int rl = i >> 5, dl = i & 31;
        int node = n0 + rl;
        if (node < n_nodes)
            out[(size_t)node * 128 + dblk + dl] = hstage[rl * 33 + dl];
    }
}

// ============================ rescale: out /= max(||row||, eps) ============================
__global__ __launch_bounds__(256) void rescale_kernel(float* __restrict__ out, int N) {
    int i = blockIdx.x * blockDim.x + threadIdx.x;
    int n = i >> 5, lane = i & 31;
    if (n >= N) return;
    float inv = 1.f / fmaxf(sqrtf(__ldg(g_ss + n)), 1e-12f);
    float4* p = reinterpret_cast<float4*>(out) + (size_t)n * 32 + lane;
    float4 v = *p;
    *p = make_float4(v.x * inv, v.y * inv, v.z * inv, v.w * inv);
}

// ============================ launch ============================
extern "C" void kernel_launch(void* const* d_in, const int* in_sizes, int n_in,
                              void* d_out, int out_size) {
    const float* ent   = (const float*)d_in[0];
    const float* erb   = (const float*)d_in[2];
    const float* onorm = (const float*)d_in[3];
    const float* Wn    = (const float*)d_in[4];
    const float* w_ih  = (const float*)d_in[5];
    const float* w_hh  = (const float*)d_in[6];
    const float* b_ih  = (const float*)d_in[7];
    const float* b_hh  = (const float*)d_in[8];
    const int* node_id = (const int*)d_in[9];
    const int* esrc    = (const int*)d_in[10];
    const int* edst    = (const int*)d_in[11];
    int N = in_sizes[3];
    int E = in_sizes[10];
    float* out = (float*)d_out;
    int npad = ((N + 127) / 128) * 128;
    if (npad > NPAD_MAX) npad = NPAD_MAX;

    cudaFuncSetAttribute(gemm_kernel, cudaFuncAttributeMaxDynamicSharedMemorySize, GEMM_SMEM);

    prep_kernel<<<513, 256>>>(Wn, w_ih, w_hh, b_ih, b_hh);
    zero_kernel<<<512, 256>>>(N, npad);
    int warps_needed = (E + 3) / 4;
    scatter_kernel<<<(warps_needed + 7) / 8, 256>>>(ent, node_id, esrc, edst, E);
    build_x_kernel<<<(npad * 32 + 255) / 256, 256>>>(erb, onorm, N, npad);
    dim3 ggrid(npad / 128, 4);
    gemm_kernel<<<ggrid, 256, GEMM_SMEM>>>(erb, out, N);
    rescale_kernel<<<(N * 32 + 255) / 256, 256>>>(out, N);
}

// round 9
// speedup vs baseline: 1.2117x; 1.2117x over previous
#include <cuda_runtime.h>
#include <cuda_bf16.h>
#include <cstdint>
#include <math.h>

#define D 128
#define NMAX 100000
#define NPAD_MAX 100096

// ---- scratch (static device globals; no runtime allocation) ----
static __device__ float g_agg[(size_t)NMAX * D];                // scatter-sum of gathered rows
static __device__ __nv_bfloat16 g_Xhi[(size_t)NPAD_MAX * 256];  // X hi split
static __device__ __nv_bfloat16 g_Xlo[(size_t)NPAD_MAX * 256];  // X lo split
static __device__ __nv_bfloat16 g_B[512 * 768];                 // gate-interleaved rows d*4+gate
static __device__ float g_bias[512];                            // br, bz, bxn, bhh_n
static __device__ float g_ss[NPAD_MAX];                         // per-node sum of squares

// ============================ PTX helpers (plain sm_103) ============================
__device__ __forceinline__ uint32_t smem_u32(const void* p) {
    uint32_t a;
    asm("{ .reg .u64 t; cvta.to.shared.u64 t, %1; cvt.u32.u64 %0, t; }" : "=r"(a) : "l"(p));
    return a;
}
__device__ __forceinline__ void cp_async16(uint32_t dst, const void* src) {
    asm volatile("cp.async.cg.shared.global [%0], [%1], 16;" :: "r"(dst), "l"(src));
}
__device__ __forceinline__ void ldm_x4(uint32_t* r, uint32_t addr) {
    asm volatile("ldmatrix.sync.aligned.m8n8.x4.shared.b16 {%0,%1,%2,%3}, [%4];"
                 : "=r"(r[0]), "=r"(r[1]), "=r"(r[2]), "=r"(r[3]) : "r"(addr));
}
__device__ __forceinline__ void mma_bf16(float* c, const uint32_t* a, uint32_t b0, uint32_t b1) {
    asm volatile(
        "mma.sync.aligned.m16n8k16.row.col.f32.bf16.bf16.f32 "
        "{%0,%1,%2,%3}, {%4,%5,%6,%7}, {%8,%9}, {%0,%1,%2,%3};"
        : "+f"(c[0]), "+f"(c[1]), "+f"(c[2]), "+f"(c[3])
        : "r"(a[0]), "r"(a[1]), "r"(a[2]), "r"(a[3]), "r"(b0), "r"(b1));
}
__device__ __forceinline__ float sigmoidf_(float x) { return 1.f / (1.f + expf(-x)); }

// ============================ prep: folded B (bf16 hi/lo, gate-interleaved) + biases =====
// Logical row n = gate*128 + d; stored at row' = d*4 + gate.
__global__ void prep_kernel(const float* __restrict__ W, const float* __restrict__ w_ih,
                            const float* __restrict__ w_hh, const float* __restrict__ b_ih,
                            const float* __restrict__ b_hh) {
    int n = blockIdx.x;
    int k = threadIdx.x;
    if (n == 512) {
        if (k < 128) {
            g_bias[k]       = b_ih[k] + b_hh[k];
            g_bias[128 + k] = b_ih[128 + k] + b_hh[128 + k];
            g_bias[256 + k] = b_ih[256 + k];
            g_bias[384 + k] = b_hh[256 + k];
        }
        return;
    }
    float v;
    if (k < 128) {
        if (n < 384) {
            float acc = 0.f;
            for (int j = 0; j < 128; j++) acc = fmaf(W[k * 128 + j], w_ih[n * 256 + j], acc);
            v = acc;
        } else v = 0.f;
    } else {
        if (n < 256)      v = w_ih[n * 256 + k] + w_hh[n * 128 + (k - 128)];
        else if (n < 384) v = w_ih[n * 256 + k];
        else              v = w_hh[(n - 128) * 128 + (k - 128)];
    }
    __nv_bfloat16 hi = __float2bfloat16_rn(v);
    __nv_bfloat16 lo = __float2bfloat16_rn(v - __bfloat162float(hi));
    int rp = (n & 127) * 4 + (n >> 7);   // gate-interleaved row
    g_B[rp * 768 + k] = hi;
    g_B[rp * 768 + 256 + k] = hi;
    g_B[rp * 768 + 512 + k] = lo;
}

// ============================ zero / scatter ============================
__global__ void zero_kernel(int N, int npad) {
    size_t total = (size_t)N * 32;
    float4* p = reinterpret_cast<float4*>(g_agg);
    for (size_t i = blockIdx.x * (size_t)blockDim.x + threadIdx.x; i < total;
         i += (size_t)gridDim.x * blockDim.x)
        p[i] = make_float4(0.f, 0.f, 0.f, 0.f);
    for (int i = blockIdx.x * blockDim.x + threadIdx.x; i < npad;
         i += gridDim.x * blockDim.x)
        g_ss[i] = 0.f;
}

// 4 edges per warp; reads ent rows directly via node_id indirection.
__global__ __launch_bounds__(256) void scatter_kernel(const float* __restrict__ ent,
                                                      const int* __restrict__ node_id,
                                                      const int* __restrict__ esrc,
                                                      const int* __restrict__ edst, int E) {
    int warp = (int)((blockIdx.x * (size_t)blockDim.x + threadIdx.x) >> 5);
    int lane = threadIdx.x & 31;
    int e0 = warp * 4;
    if (e0 >= E) return;
    int dst[4], row[4];
    #pragma unroll
    for (int j = 0; j < 4; j++) {
        if (e0 + j < E) {
            int s = __ldg(esrc + e0 + j);
            dst[j] = __ldg(edst + e0 + j);
            row[j] = __ldg(node_id + s);
        } else {
            dst[j] = -1; row[j] = 0;
        }
    }
    float4 v[4];
    #pragma unroll
    for (int j = 0; j < 4; j++)
        v[j] = __ldg(reinterpret_cast<const float4*>(ent) + (size_t)row[j] * 32 + lane);
    #pragma unroll
    for (int j = 0; j < 4; j++)
        if (dst[j] >= 0)
            atomicAdd(reinterpret_cast<float4*>(g_agg) + (size_t)dst[j] * 32 + lane, v[j]);
}

// ============================ build X (hi/lo bf16 split) ============================
__global__ __launch_bounds__(256) void build_x_kernel(const float* __restrict__ erb,
                                                      const float* __restrict__ onorm,
                                                      int N, int npad) {
    int i = blockIdx.x * blockDim.x + threadIdx.x;
    int node = i >> 5, lane = i & 31;
    if (node >= npad) return;
    float x[8];
    if (node < N) {
        float sc = __ldg(onorm + node);
        float4 a = __ldg(reinterpret_cast<const float4*>(g_agg) + (size_t)node * 32 + lane);
        float4 e = __ldg(reinterpret_cast<const float4*>(erb) + (size_t)node * 32 + lane);
        x[0] = a.x * sc; x[1] = a.y * sc; x[2] = a.z * sc; x[3] = a.w * sc;
        x[4] = e.x; x[5] = e.y; x[6] = e.z; x[7] = e.w;
    } else {
        #pragma unroll
        for (int q = 0; q < 8; q++) x[q] = 0.f;
    }
    unsigned short hs[8], ls[8];
    #pragma unroll
    for (int q = 0; q < 8; q++) {
        __nv_bfloat16 hb = __float2bfloat16_rn(x[q]);
        __nv_bfloat16 lb = __float2bfloat16_rn(x[q] - __bfloat162float(hb));
        hs[q] = *reinterpret_cast<unsigned short*>(&hb);
        ls[q] = *reinterpret_cast<unsigned short*>(&lb);
    }
    uint2* dhi0 = reinterpret_cast<uint2*>(g_Xhi + (size_t)node * 256 + lane * 4);
    uint2* dhi1 = reinterpret_cast<uint2*>(g_Xhi + (size_t)node * 256 + 128 + lane * 4);
    uint2* dlo0 = reinterpret_cast<uint2*>(g_Xlo + (size_t)node * 256 + lane * 4);
    uint2* dlo1 = reinterpret_cast<uint2*>(g_Xlo + (size_t)node * 256 + 128 + lane * 4);
    *dhi0 = make_uint2((uint32_t)hs[0] | ((uint32_t)hs[1] << 16), (uint32_t)hs[2] | ((uint32_t)hs[3] << 16));
    *dhi1 = make_uint2((uint32_t)hs[4] | ((uint32_t)hs[5] << 16), (uint32_t)hs[6] | ((uint32_t)hs[7] << 16));
    *dlo0 = make_uint2((uint32_t)ls[0] | ((uint32_t)ls[1] << 16), (uint32_t)ls[2] | ((uint32_t)ls[3] << 16));
    *dlo1 = make_uint2((uint32_t)ls[4] | ((uint32_t)ls[5] << 16), (uint32_t)ls[6] | ((uint32_t)ls[7] << 16));
}

// ============================ fused GEMM + GRU epilogue (v2) ============================
// y-block b: dims [32b, 32b+32) x 4 interleaved gates (cols = dl*4+gate).
// Mainloop identical to round-7 GEMM. Epilogue: dump acc -> smem (stride 136,
// half-offset 68 for conflict-free re-read), then thread-per-(node,16 dims)
// gate math in fp32, direct store to out, sumsq atomics into g_ss.
#define STAGE_BYTES 32768
#define GEMM_SMEM (3 * STAGE_BYTES)
#define HST_STRIDE 136

__global__ __launch_bounds__(256, 2) void gemm_kernel(const float* __restrict__ erb,
                                                      float* __restrict__ out, int n_nodes) {
    extern __shared__ char smc[];
    uint32_t sbase = smem_u32(smc);
    int tid = threadIdx.x, lane = tid & 31, w = tid >> 5;
    int n0 = blockIdx.x * 128;
    int d0 = blockIdx.y * 128;          // interleaved-col block base
    int dblk = blockIdx.y * 32;         // dim block base
    int wm = w & 3, wn = w >> 2;
    int m0 = wm * 32, nw0 = wn * 64;

    float acc[2][8][4];
    #pragma unroll
    for (int a = 0; a < 2; a++)
        #pragma unroll
        for (int b = 0; b < 8; b++)
            #pragma unroll
            for (int c = 0; c < 4; c++) acc[a][b][c] = 0.f;

    auto load_chunk = [&](int c, int st) {
        const __nv_bfloat16* X = (c >= 4 && c < 8) ? g_Xlo : g_Xhi;
        const __nv_bfloat16* Asrc = X + (size_t)n0 * 256 + (c & 3) * 64;
        const __nv_bfloat16* Bsrc = g_B + (size_t)d0 * 768 + c * 64;
        uint32_t abase = sbase + st * STAGE_BYTES;
        uint32_t bbase = abase + 16384;
        #pragma unroll
        for (int i = 0; i < 4; i++) {
            int e = i * 256 + tid;
            int row = e >> 3, ch = e & 7;
            cp_async16(abase + (row * 8 + (ch ^ (row & 7))) * 16,
                       Asrc + (size_t)row * 256 + ch * 8);
        }
        #pragma unroll
        for (int i = 0; i < 4; i++) {
            int e = i * 256 + tid;
            int row = e >> 3, ch = e & 7;
            cp_async16(bbase + (row * 8 + (ch ^ (row & 7))) * 16,
                       Bsrc + (size_t)row * 768 + ch * 8);
        }
        asm volatile("cp.async.commit_group;" ::: "memory");
    };

    load_chunk(0, 0);
    load_chunk(1, 1);

    for (int i = 0; i < 12; i++) {
        int st = i % 3;
        if (i < 11) asm volatile("cp.async.wait_group 1;" ::: "memory");
        else        asm volatile("cp.async.wait_group 0;" ::: "memory");
        __syncthreads();
        if (i + 2 < 12) load_chunk(i + 2, (i + 2) % 3);
        uint32_t abase = sbase + st * STAGE_BYTES;
        uint32_t bbase = abase + 16384;
        #pragma unroll
        for (int k16 = 0; k16 < 4; k16++) {
            uint32_t af[2][4], bf[4][4];
            #pragma unroll
            for (int mi = 0; mi < 2; mi++) {
                int row = m0 + mi * 16 + (lane & 15);
                int ch = k16 * 2 + (lane >> 4);
                ldm_x4(af[mi], abase + (row * 8 + (ch ^ (row & 7))) * 16);
            }
            #pragma unroll
            for (int j = 0; j < 4; j++) {
                int row = nw0 + j * 16 + (lane & 15);
                int ch = k16 * 2 + (lane >> 4);
                ldm_x4(bf[j], bbase + (row * 8 + (ch ^ (row & 7))) * 16);
            }
            #pragma unroll
            for (int mi = 0; mi < 2; mi++)
                #pragma unroll
                for (int j = 0; j < 4; j++) {
                    mma_bf16(acc[mi][2 * j],     af[mi], bf[j][0], bf[j][2]);
                    mma_bf16(acc[mi][2 * j + 1], af[mi], bf[j][1], bf[j][3]);
                }
        }
    }
    __syncthreads();   // pipeline buffers dead; reuse as hstage

    // ---- dump acc to smem: hstage[node][coloff], coloff = (nw0?68:0)+j*8+tc ----
    float* hst = reinterpret_cast<float*>(smc);   // 128 x HST_STRIDE floats (69.6 KB)
    {
        int tr = lane >> 2, tc = (lane & 3) * 2;
        int cbase = (nw0 ? 68 : 0) + tc;
        #pragma unroll
        for (int mi = 0; mi < 2; mi++) {
            #pragma unroll
            for (int j = 0; j < 8; j++) {
                float* cp = acc[mi][j];
                int r0 = m0 + mi * 16 + tr;
                int co = cbase + j * 8;
                *reinterpret_cast<float2*>(hst + r0 * HST_STRIDE + co) = make_float2(cp[0], cp[1]);
                *reinterpret_cast<float2*>(hst + (r0 + 8) * HST_STRIDE + co) = make_float2(cp[2], cp[3]);
            }
        }
    }
    __syncthreads();

    // ---- epilogue: thread t handles node (t>>1), dims dh*16..dh*16+16 ----
    {
        int nl = tid >> 1, dh = tid & 1;
        int node = n0 + nl;
        bool valid = node < n_nodes;
        const float4* ebase = reinterpret_cast<const float4*>(erb + (size_t)node * 128 + dblk + dh * 16);
        const float4* grow = reinterpret_cast<const float4*>(hst + nl * HST_STRIDE + dh * 68);
        float4* obase = reinterpret_cast<float4*>(out + (size_t)node * 128 + dblk + dh * 16);
        float ss = 0.f;
        #pragma unroll
        for (int i = 0; i < 4; i++) {
            float4 e = valid ? __ldg(ebase + i) : make_float4(0.f, 0.f, 0.f, 0.f);
            const float* ef = &e.x;
            float hv[4];
            #pragma unroll
            for (int q = 0; q < 4; q++) {
                int d = dblk + dh * 16 + i * 4 + q;
                float4 g = grow[i * 4 + q];   // (r,z,xn,hn) preacts for dim d
                float r_ = sigmoidf_(g.x + __ldg(g_bias + d));
                float z_ = sigmoidf_(g.y + __ldg(g_bias + 128 + d));
                float nn = tanhf(g.z + __ldg(g_bias + 256 + d) + r_ * (g.w + __ldg(g_bias + 384 + d)));
                float h = fmaxf((1.f - z_) * nn + z_ * ef[q], 0.f);
                ss += h * h;
                hv[q] = h;
            }
            if (valid) obase[i] = make_float4(hv[0], hv[1], hv[2], hv[3]);
        }
        ss += __shfl_xor_sync(0xFFFFFFFFu, ss, 1);
        if (valid && dh == 0) atomicAdd(&g_ss[node], ss);
    }
}

// ============================ rescale: out /= max(||row||, eps) ============================
__global__ __launch_bounds__(256) void rescale_kernel(float* __restrict__ out, int N) {
    int i = blockIdx.x * blockDim.x + threadIdx.x;
    int n = i >> 5, lane = i & 31;
    if (n >= N) return;
    float inv = 1.f / fmaxf(sqrtf(__ldg(g_ss + n)), 1e-12f);
    float4* p = reinterpret_cast<float4*>(out) + (size_t)n * 32 + lane;
    float4 v = *p;
    *p = make_float4(v.x * inv, v.y * inv, v.z * inv, v.w * inv);
}

// ============================ launch ============================
extern "C" void kernel_launch(void* const* d_in, const int* in_sizes, int n_in,
                              void* d_out, int out_size) {
    const float* ent   = (const float*)d_in[0];
    const float* erb   = (const float*)d_in[2];
    const float* onorm = (const float*)d_in[3];
    const float* Wn    = (const float*)d_in[4];
    const float* w_ih  = (const float*)d_in[5];
    const float* w_hh  = (const float*)d_in[6];
    const float* b_ih  = (const float*)d_in[7];
    const float* b_hh  = (const float*)d_in[8];
    const int* node_id = (const int*)d_in[9];
    const int* esrc    = (const int*)d_in[10];
    const int* edst    = (const int*)d_in[11];
    int N = in_sizes[3];
    int E = in_sizes[10];
    float* out = (float*)d_out;
    int npad = ((N + 127) / 128) * 128;
    if (npad > NPAD_MAX) npad = NPAD_MAX;

    cudaFuncSetAttribute(gemm_kernel, cudaFuncAttributeMaxDynamicSharedMemorySize, GEMM_SMEM);

    prep_kernel<<<513, 256>>>(Wn, w_ih, w_hh, b_ih, b_hh);
    zero_kernel<<<512, 256>>>(N, npad);
    int warps_needed = (E + 3) / 4;
    scatter_kernel<<<(warps_needed + 7) / 8, 256>>>(ent, node_id, esrc, edst, E);
    build_x_kernel<<<(npad * 32 + 255) / 256, 256>>>(erb, onorm, N, npad);
    dim3 ggrid(npad / 128, 4);
    gemm_kernel<<<ggrid, 256, GEMM_SMEM>>>(erb, out, N);
    rescale_kernel<<<(N * 32 + 255) / 256, 256>>>(out, N);
}

// round 10
// speedup vs baseline: 1.2218x; 1.0084x over previous
#include <cuda_runtime.h>
#include <cuda_bf16.h>
#include <cstdint>
#include <math.h>

#define D 128
#define NMAX 100000
#define NPAD_MAX 100096

// ---- scratch (static device globals; no runtime allocation) ----
static __device__ float g_agg[(size_t)NMAX * D];                // scatter-sum of gathered rows
static __device__ __nv_bfloat16 g_Xhi[(size_t)NPAD_MAX * 256];  // X hi split
static __device__ __nv_bfloat16 g_Xlo[(size_t)NPAD_MAX * 256];  // X lo split
static __device__ __nv_bfloat16 g_B[512 * 768];                 // [n][ Bhi | Bhi | Blo ]
static __device__ float g_C[(size_t)NPAD_MAX * 512];            // GEMM result (gate preacts)
static __device__ float g_bias[512];                            // br, bz, bxn, bhh_n

// ============================ PTX helpers (plain sm_103) ============================
__device__ __forceinline__ uint32_t smem_u32(const void* p) {
    uint32_t a;
    asm("{ .reg .u64 t; cvta.to.shared.u64 t, %1; cvt.u32.u64 %0, t; }" : "=r"(a) : "l"(p));
    return a;
}
__device__ __forceinline__ void cp_async16(uint32_t dst, const void* src) {
    asm volatile("cp.async.cg.shared.global [%0], [%1], 16;" :: "r"(dst), "l"(src));
}
__device__ __forceinline__ void ldm_x4(uint32_t* r, uint32_t addr) {
    asm volatile("ldmatrix.sync.aligned.m8n8.x4.shared.b16 {%0,%1,%2,%3}, [%4];"
                 : "=r"(r[0]), "=r"(r[1]), "=r"(r[2]), "=r"(r[3]) : "r"(addr));
}
__device__ __forceinline__ void mma_bf16(float* c, const uint32_t* a, uint32_t b0, uint32_t b1) {
    asm volatile(
        "mma.sync.aligned.m16n8k16.row.col.f32.bf16.bf16.f32 "
        "{%0,%1,%2,%3}, {%4,%5,%6,%7}, {%8,%9}, {%0,%1,%2,%3};"
        : "+f"(c[0]), "+f"(c[1]), "+f"(c[2]), "+f"(c[3])
        : "r"(a[0]), "r"(a[1]), "r"(a[2]), "r"(a[3]), "r"(b0), "r"(b1));
}
__device__ __forceinline__ float sigmoidf_(float x) { return 1.f / (1.f + expf(-x)); }

// ============================ prep: folded B (bf16 hi/lo) + biases ============================
__global__ void prep_kernel(const float* __restrict__ W, const float* __restrict__ w_ih,
                            const float* __restrict__ w_hh, const float* __restrict__ b_ih,
                            const float* __restrict__ b_hh) {
    int n = blockIdx.x;
    int k = threadIdx.x;
    if (n == 512) {
        if (k < 128) {
            g_bias[k]       = b_ih[k] + b_hh[k];
            g_bias[128 + k] = b_ih[128 + k] + b_hh[128 + k];
            g_bias[256 + k] = b_ih[256 + k];
            g_bias[384 + k] = b_hh[256 + k];
        }
        return;
    }
    float v;
    if (k < 128) {
        if (n < 384) {
            float acc = 0.f;
            for (int j = 0; j < 128; j++) acc = fmaf(W[k * 128 + j], w_ih[n * 256 + j], acc);
            v = acc;
        } else v = 0.f;
    } else {
        if (n < 256)      v = w_ih[n * 256 + k] + w_hh[n * 128 + (k - 128)];
        else if (n < 384) v = w_ih[n * 256 + k];
        else              v = w_hh[(n - 128) * 128 + (k - 128)];
    }
    __nv_bfloat16 hi = __float2bfloat16_rn(v);
    __nv_bfloat16 lo = __float2bfloat16_rn(v - __bfloat162float(hi));
    g_B[n * 768 + k] = hi;
    g_B[n * 768 + 256 + k] = hi;
    g_B[n * 768 + 512 + k] = lo;
}

// ============================ zero / scatter ============================
__global__ void zero_kernel(int N) {
    size_t total = (size_t)N * 32;
    float4* p = reinterpret_cast<float4*>(g_agg);
    for (size_t i = blockIdx.x * (size_t)blockDim.x + threadIdx.x; i < total;
         i += (size_t)gridDim.x * blockDim.x)
        p[i] = make_float4(0.f, 0.f, 0.f, 0.f);
}

// 4 edges per warp; reads ent rows directly via node_id indirection.
__global__ __launch_bounds__(256) void scatter_kernel(const float* __restrict__ ent,
                                                      const int* __restrict__ node_id,
                                                      const int* __restrict__ esrc,
                                                      const int* __restrict__ edst, int E) {
    int warp = (int)((blockIdx.x * (size_t)blockDim.x + threadIdx.x) >> 5);
    int lane = threadIdx.x & 31;
    int e0 = warp * 4;
    if (e0 >= E) return;
    int dst[4], row[4];
    #pragma unroll
    for (int j = 0; j < 4; j++) {
        if (e0 + j < E) {
            int s = __ldg(esrc + e0 + j);
            dst[j] = __ldg(edst + e0 + j);
            row[j] = __ldg(node_id + s);
        } else {
            dst[j] = -1; row[j] = 0;
        }
    }
    float4 v[4];
    #pragma unroll
    for (int j = 0; j < 4; j++)
        v[j] = __ldg(reinterpret_cast<const float4*>(ent) + (size_t)row[j] * 32 + lane);
    #pragma unroll
    for (int j = 0; j < 4; j++)
        if (dst[j] >= 0)
            atomicAdd(reinterpret_cast<float4*>(g_agg) + (size_t)dst[j] * 32 + lane, v[j]);
}

// ============================ build X (hi/lo bf16 split) ============================
__global__ __launch_bounds__(256) void build_x_kernel(const float* __restrict__ erb,
                                                      const float* __restrict__ onorm,
                                                      int N, int npad) {
    int i = blockIdx.x * blockDim.x + threadIdx.x;
    int node = i >> 5, lane = i & 31;
    if (node >= npad) return;
    float x[8];
    if (node < N) {
        float sc = __ldg(onorm + node);
        float4 a = __ldg(reinterpret_cast<const float4*>(g_agg) + (size_t)node * 32 + lane);
        float4 e = __ldg(reinterpret_cast<const float4*>(erb) + (size_t)node * 32 + lane);
        x[0] = a.x * sc; x[1] = a.y * sc; x[2] = a.z * sc; x[3] = a.w * sc;
        x[4] = e.x; x[5] = e.y; x[6] = e.z; x[7] = e.w;
    } else {
        #pragma unroll
        for (int q = 0; q < 8; q++) x[q] = 0.f;
    }
    unsigned short hs[8], ls[8];
    #pragma unroll
    for (int q = 0; q < 8; q++) {
        __nv_bfloat16 hb = __float2bfloat16_rn(x[q]);
        __nv_bfloat16 lb = __float2bfloat16_rn(x[q] - __bfloat162float(hb));
        hs[q] = *reinterpret_cast<unsigned short*>(&hb);
        ls[q] = *reinterpret_cast<unsigned short*>(&lb);
    }
    uint2* dhi0 = reinterpret_cast<uint2*>(g_Xhi + (size_t)node * 256 + lane * 4);
    uint2* dhi1 = reinterpret_cast<uint2*>(g_Xhi + (size_t)node * 256 + 128 + lane * 4);
    uint2* dlo0 = reinterpret_cast<uint2*>(g_Xlo + (size_t)node * 256 + lane * 4);
    uint2* dlo1 = reinterpret_cast<uint2*>(g_Xlo + (size_t)node * 256 + 128 + lane * 4);
    *dhi0 = make_uint2((uint32_t)hs[0] | ((uint32_t)hs[1] << 16), (uint32_t)hs[2] | ((uint32_t)hs[3] << 16));
    *dhi1 = make_uint2((uint32_t)hs[4] | ((uint32_t)hs[5] << 16), (uint32_t)hs[6] | ((uint32_t)hs[7] << 16));
    *dlo0 = make_uint2((uint32_t)ls[0] | ((uint32_t)ls[1] << 16), (uint32_t)ls[2] | ((uint32_t)ls[3] << 16));
    *dlo1 = make_uint2((uint32_t)ls[4] | ((uint32_t)ls[5] << 16), (uint32_t)ls[6] | ((uint32_t)ls[7] << 16));
}

// ============================ GEMM: C[npad,512] = Xv[npad,768] @ Bv[768,512]^T =========
// Virtual K chunks: 0-3 Xhi·Bhi, 4-7 Xlo·Bhi, 8-11 Xhi·Blo.
// hn gate (d0==384): B rows exactly 0 for k<128 → only chunks {2,3,6,7,10,11}.
// GRID AXES SWAPPED (x = gate block, y = node block) so the 4 CTAs sharing an
// A tile are rasterized adjacently → A chunk loads hit L2 instead of DRAM.
#define STAGE_BYTES 32768
#define GEMM_SMEM (3 * STAGE_BYTES)

__global__ __launch_bounds__(256, 2) void gemm_kernel(int npad) {
    extern __shared__ char smc[];
    uint32_t sbase = smem_u32(smc);
    int tid = threadIdx.x, lane = tid & 31, w = tid >> 5;
    int n0 = blockIdx.y * 128;          // node tile (slow axis)
    int d0 = blockIdx.x * 128;          // gate tile (fast axis → L2 sharing of A)
    int wm = w & 3, wn = w >> 2;
    int m0 = wm * 32, nw0 = wn * 64;

    const int map3[6] = {2, 3, 6, 7, 10, 11};
    bool is_hn = (d0 == 384);
    int nch = is_hn ? 6 : 12;

    float acc[2][8][4];
    #pragma unroll
    for (int a = 0; a < 2; a++)
        #pragma unroll
        for (int b = 0; b < 8; b++)
            #pragma unroll
            for (int c = 0; c < 4; c++) acc[a][b][c] = 0.f;

    auto load_chunk = [&](int c, int st) {
        const __nv_bfloat16* X = (c >= 4 && c < 8) ? g_Xlo : g_Xhi;
        const __nv_bfloat16* Asrc = X + (size_t)n0 * 256 + (c & 3) * 64;
        const __nv_bfloat16* Bsrc = g_B + (size_t)d0 * 768 + c * 64;
        uint32_t abase = sbase + st * STAGE_BYTES;
        uint32_t bbase = abase + 16384;
        #pragma unroll
        for (int i = 0; i < 4; i++) {
            int e = i * 256 + tid;
            int row = e >> 3, ch = e & 7;
            cp_async16(abase + (row * 8 + (ch ^ (row & 7))) * 16,
                       Asrc + (size_t)row * 256 + ch * 8);
        }
        #pragma unroll
        for (int i = 0; i < 4; i++) {
            int e = i * 256 + tid;
            int row = e >> 3, ch = e & 7;
            cp_async16(bbase + (row * 8 + (ch ^ (row & 7))) * 16,
                       Bsrc + (size_t)row * 768 + ch * 8);
        }
        asm volatile("cp.async.commit_group;" ::: "memory");
    };

    auto chunk_of = [&](int i) { return is_hn ? map3[i] : i; };

    load_chunk(chunk_of(0), 0);
    load_chunk(chunk_of(1), 1);

    for (int i = 0; i < nch; i++) {
        int st = i % 3;
        if (i < nch - 1) asm volatile("cp.async.wait_group 1;" ::: "memory");
        else             asm volatile("cp.async.wait_group 0;" ::: "memory");
        __syncthreads();
        // safe: barrier above proves all warps finished reading stage (i+2)%3.
        if (i + 2 < nch) load_chunk(chunk_of(i + 2), (i + 2) % 3);
        uint32_t abase = sbase + st * STAGE_BYTES;
        uint32_t bbase = abase + 16384;
        #pragma unroll
        for (int k16 = 0; k16 < 4; k16++) {
            uint32_t af[2][4], bf[4][4];
            #pragma unroll
            for (int mi = 0; mi < 2; mi++) {
                int row = m0 + mi * 16 + (lane & 15);
                int ch = k16 * 2 + (lane >> 4);
                ldm_x4(af[mi], abase + (row * 8 + (ch ^ (row & 7))) * 16);
            }
            #pragma unroll
            for (int j = 0; j < 4; j++) {
                int row = nw0 + j * 16 + (lane & 15);
                int ch = k16 * 2 + (lane >> 4);
                ldm_x4(bf[j], bbase + (row * 8 + (ch ^ (row & 7))) * 16);
            }
            #pragma unroll
            for (int mi = 0; mi < 2; mi++)
                #pragma unroll
                for (int j = 0; j < 4; j++) {
                    mma_bf16(acc[mi][2 * j],     af[mi], bf[j][0], bf[j][2]);
                    mma_bf16(acc[mi][2 * j + 1], af[mi], bf[j][1], bf[j][3]);
                }
        }
    }

    int tr = lane >> 2, tc = (lane & 3) * 2;
    #pragma unroll
    for (int mi = 0; mi < 2; mi++) {
        #pragma unroll
        for (int j = 0; j < 8; j++) {
            int node = n0 + m0 + mi * 16 + tr;
            int d = d0 + nw0 + j * 8 + tc;
            float* cp = acc[mi][j];
            *reinterpret_cast<float2*>(g_C + (size_t)node * 512 + d) =
                make_float2(cp[0], cp[1]);
            *reinterpret_cast<float2*>(g_C + (size_t)(node + 8) * 512 + d) =
                make_float2(cp[2], cp[3]);
        }
    }
}

// ============================ epilogue: gates + relu + row norm ============================
__global__ __launch_bounds__(256) void epilogue_kernel(const float* __restrict__ erb,
                                                       float* __restrict__ out, int N) {
    int gw = (int)((blockIdx.x * (size_t)blockDim.x + threadIdx.x) >> 5);
    int lane = threadIdx.x & 31;
    if (gw >= N) return;
    const float4* C4 = reinterpret_cast<const float4*>(g_C + (size_t)gw * 512);
    float4 r4 = __ldg(C4 + lane);
    float4 z4 = __ldg(C4 + 32 + lane);
    float4 x4 = __ldg(C4 + 64 + lane);
    float4 h4 = __ldg(C4 + 96 + lane);
    float4 e4 = __ldg(reinterpret_cast<const float4*>(erb) + (size_t)gw * 32 + lane);
    const float* rr = &r4.x;
    const float* zz = &z4.x;
    const float* xx = &x4.x;
    const float* hh = &h4.x;
    const float* ee = &e4.x;
    float hv[4];
    float ss = 0.f;
    #pragma unroll
    for (int i = 0; i < 4; i++) {
        int d = lane * 4 + i;
        float r = sigmoidf_(rr[i] + __ldg(g_bias + d));
        float z = sigmoidf_(zz[i] + __ldg(g_bias + 128 + d));
        float nn = tanhf(xx[i] + __ldg(g_bias + 256 + d) + r * (hh[i] + __ldg(g_bias + 384 + d)));
        float h = fmaxf((1.f - z) * nn + z * ee[i], 0.f);
        ss += h * h;
        hv[i] = h;
    }
    #pragma unroll
    for (int o = 16; o; o >>= 1) ss += __shfl_xor_sync(0xFFFFFFFFu, ss, o);
    float inv = 1.f / fmaxf(sqrtf(ss), 1e-12f);
    reinterpret_cast<float4*>(out)[(size_t)gw * 32 + lane] =
        make_float4(hv[0] * inv, hv[1] * inv, hv[2] * inv, hv[3] * inv);
}

// ============================ launch ============================
extern "C" void kernel_launch(void* const* d_in, const int* in_sizes, int n_in,
                              void* d_out, int out_size) {
    const float* ent   = (const float*)d_in[0];
    const float* erb   = (const float*)d_in[2];
    const float* onorm = (const float*)d_in[3];
    const float* Wn    = (const float*)d_in[4];
    const float* w_ih  = (const float*)d_in[5];
    const float* w_hh  = (const float*)d_in[6];
    const float* b_ih  = (const float*)d_in[7];
    const float* b_hh  = (const float*)d_in[8];
    const int* node_id = (const int*)d_in[9];
    const int* esrc    = (const int*)d_in[10];
    const int* edst    = (const int*)d_in[11];
    int N = in_sizes[3];
    int E = in_sizes[10];
    float* out = (float*)d_out;
    int npad = ((N + 127) / 128) * 128;
    if (npad > NPAD_MAX) npad = NPAD_MAX;

    cudaFuncSetAttribute(gemm_kernel, cudaFuncAttributeMaxDynamicSharedMemorySize, GEMM_SMEM);

    prep_kernel<<<513, 256>>>(Wn, w_ih, w_hh, b_ih, b_hh);
    zero_kernel<<<512, 256>>>(N);
    int warps_needed = (E + 3) / 4;
    scatter_kernel<<<(warps_needed + 7) / 8, 256>>>(ent, node_id, esrc, edst, E);
    build_x_kernel<<<(npad * 32 + 255) / 256, 256>>>(erb, onorm, N, npad);
    dim3 ggrid(4, npad / 128);   // x = gate block (fast), y = node block (slow)
    gemm_kernel<<<ggrid, 256, GEMM_SMEM>>>(npad);
    epilogue_kernel<<<(N * 32 + 255) / 256, 256>>>(erb, out, N);
}

// round 11
// speedup vs baseline: 1.2700x; 1.0394x over previous
#include <cuda_runtime.h>
#include <cuda_bf16.h>
#include <cuda_fp16.h>
#include <cstdint>
#include <math.h>

#define D 128
#define NMAX 100000
#define NPAD_MAX 100096

// ---- scratch (static device globals; no runtime allocation) ----
static __device__ float g_agg[(size_t)NMAX * D];                // scatter-sum of gathered rows
static __device__ __nv_bfloat16 g_Xhi[(size_t)NPAD_MAX * 256];  // X hi split
static __device__ __nv_bfloat16 g_Xlo[(size_t)NPAD_MAX * 256];  // X lo split
static __device__ __nv_bfloat16 g_B[512 * 768];                 // [n][ Bhi | Bhi | Blo ]
static __device__ __half g_C[(size_t)NPAD_MAX * 512];           // GEMM result (fp16 preacts)
static __device__ float g_bias[512];                            // br, bz, bxn, bhh_n

// ============================ PTX helpers (plain sm_103) ============================
__device__ __forceinline__ uint32_t smem_u32(const void* p) {
    uint32_t a;
    asm("{ .reg .u64 t; cvta.to.shared.u64 t, %1; cvt.u32.u64 %0, t; }" : "=r"(a) : "l"(p));
    return a;
}
__device__ __forceinline__ void cp_async16(uint32_t dst, const void* src) {
    asm volatile("cp.async.cg.shared.global [%0], [%1], 16;" :: "r"(dst), "l"(src));
}
__device__ __forceinline__ void ldm_x4(uint32_t* r, uint32_t addr) {
    asm volatile("ldmatrix.sync.aligned.m8n8.x4.shared.b16 {%0,%1,%2,%3}, [%4];"
                 : "=r"(r[0]), "=r"(r[1]), "=r"(r[2]), "=r"(r[3]) : "r"(addr));
}
__device__ __forceinline__ void mma_bf16(float* c, const uint32_t* a, uint32_t b0, uint32_t b1) {
    asm volatile(
        "mma.sync.aligned.m16n8k16.row.col.f32.bf16.bf16.f32 "
        "{%0,%1,%2,%3}, {%4,%5,%6,%7}, {%8,%9}, {%0,%1,%2,%3};"
        : "+f"(c[0]), "+f"(c[1]), "+f"(c[2]), "+f"(c[3])
        : "r"(a[0]), "r"(a[1]), "r"(a[2]), "r"(a[3]), "r"(b0), "r"(b1));
}
__device__ __forceinline__ float sigmoidf_(float x) { return 1.f / (1.f + expf(-x)); }
// load 4 consecutive fp16 preacts as fp32
__device__ __forceinline__ void ld4h(float* o, const uint2* p) {
    uint2 v = __ldg(p);
    const __half2* h = reinterpret_cast<const __half2*>(&v);
    float2 a = __half22float2(h[0]);
    float2 b = __half22float2(h[1]);
    o[0] = a.x; o[1] = a.y; o[2] = b.x; o[3] = b.y;
}

// ============================ prep: folded B (bf16 hi/lo) + biases ============================
__global__ void prep_kernel(const float* __restrict__ W, const float* __restrict__ w_ih,
                            const float* __restrict__ w_hh, const float* __restrict__ b_ih,
                            const float* __restrict__ b_hh) {
    int n = blockIdx.x;
    int k = threadIdx.x;
    if (n == 512) {
        if (k < 128) {
            g_bias[k]       = b_ih[k] + b_hh[k];
            g_bias[128 + k] = b_ih[128 + k] + b_hh[128 + k];
            g_bias[256 + k] = b_ih[256 + k];
            g_bias[384 + k] = b_hh[256 + k];
        }
        return;
    }
    float v;
    if (k < 128) {
        if (n < 384) {
            float acc = 0.f;
            for (int j = 0; j < 128; j++) acc = fmaf(W[k * 128 + j], w_ih[n * 256 + j], acc);
            v = acc;
        } else v = 0.f;
    } else {
        if (n < 256)      v = w_ih[n * 256 + k] + w_hh[n * 128 + (k - 128)];
        else if (n < 384) v = w_ih[n * 256 + k];
        else              v = w_hh[(n - 128) * 128 + (k - 128)];
    }
    __nv_bfloat16 hi = __float2bfloat16_rn(v);
    __nv_bfloat16 lo = __float2bfloat16_rn(v - __bfloat162float(hi));
    g_B[n * 768 + k] = hi;
    g_B[n * 768 + 256 + k] = hi;
    g_B[n * 768 + 512 + k] = lo;
}

// ============================ zero / scatter ============================
__global__ void zero_kernel(int N) {
    size_t total = (size_t)N * 32;
    float4* p = reinterpret_cast<float4*>(g_agg);
    for (size_t i = blockIdx.x * (size_t)blockDim.x + threadIdx.x; i < total;
         i += (size_t)gridDim.x * blockDim.x)
        p[i] = make_float4(0.f, 0.f, 0.f, 0.f);
}

// 4 edges per warp; reads ent rows directly via node_id indirection.
__global__ __launch_bounds__(256) void scatter_kernel(const float* __restrict__ ent,
                                                      const int* __restrict__ node_id,
                                                      const int* __restrict__ esrc,
                                                      const int* __restrict__ edst, int E) {
    int warp = (int)((blockIdx.x * (size_t)blockDim.x + threadIdx.x) >> 5);
    int lane = threadIdx.x & 31;
    int e0 = warp * 4;
    if (e0 >= E) return;
    int dst[4], row[4];
    #pragma unroll
    for (int j = 0; j < 4; j++) {
        if (e0 + j < E) {
            int s = __ldg(esrc + e0 + j);
            dst[j] = __ldg(edst + e0 + j);
            row[j] = __ldg(node_id + s);
        } else {
            dst[j] = -1; row[j] = 0;
        }
    }
    float4 v[4];
    #pragma unroll
    for (int j = 0; j < 4; j++)
        v[j] = __ldg(reinterpret_cast<const float4*>(ent) + (size_t)row[j] * 32 + lane);
    #pragma unroll
    for (int j = 0; j < 4; j++)
        if (dst[j] >= 0)
            atomicAdd(reinterpret_cast<float4*>(g_agg) + (size_t)dst[j] * 32 + lane, v[j]);
}

// ============================ build X (hi/lo bf16 split) ============================
__global__ __launch_bounds__(256) void build_x_kernel(const float* __restrict__ erb,
                                                      const float* __restrict__ onorm,
                                                      int N, int npad) {
    int i = blockIdx.x * blockDim.x + threadIdx.x;
    int node = i >> 5, lane = i & 31;
    if (node >= npad) return;
    float x[8];
    if (node < N) {
        float sc = __ldg(onorm + node);
        float4 a = __ldg(reinterpret_cast<const float4*>(g_agg) + (size_t)node * 32 + lane);
        float4 e = __ldg(reinterpret_cast<const float4*>(erb) + (size_t)node * 32 + lane);
        x[0] = a.x * sc; x[1] = a.y * sc; x[2] = a.z * sc; x[3] = a.w * sc;
        x[4] = e.x; x[5] = e.y; x[6] = e.z; x[7] = e.w;
    } else {
        #pragma unroll
        for (int q = 0; q < 8; q++) x[q] = 0.f;
    }
    unsigned short hs[8], ls[8];
    #pragma unroll
    for (int q = 0; q < 8; q++) {
        __nv_bfloat16 hb = __float2bfloat16_rn(x[q]);
        __nv_bfloat16 lb = __float2bfloat16_rn(x[q] - __bfloat162float(hb));
        hs[q] = *reinterpret_cast<unsigned short*>(&hb);
        ls[q] = *reinterpret_cast<unsigned short*>(&lb);
    }
    uint2* dhi0 = reinterpret_cast<uint2*>(g_Xhi + (size_t)node * 256 + lane * 4);
    uint2* dhi1 = reinterpret_cast<uint2*>(g_Xhi + (size_t)node * 256 + 128 + lane * 4);
    uint2* dlo0 = reinterpret_cast<uint2*>(g_Xlo + (size_t)node * 256 + lane * 4);
    uint2* dlo1 = reinterpret_cast<uint2*>(g_Xlo + (size_t)node * 256 + 128 + lane * 4);
    *dhi0 = make_uint2((uint32_t)hs[0] | ((uint32_t)hs[1] << 16), (uint32_t)hs[2] | ((uint32_t)hs[3] << 16));
    *dhi1 = make_uint2((uint32_t)hs[4] | ((uint32_t)hs[5] << 16), (uint32_t)hs[6] | ((uint32_t)hs[7] << 16));
    *dlo0 = make_uint2((uint32_t)ls[0] | ((uint32_t)ls[1] << 16), (uint32_t)ls[2] | ((uint32_t)ls[3] << 16));
    *dlo1 = make_uint2((uint32_t)ls[4] | ((uint32_t)ls[5] << 16), (uint32_t)ls[6] | ((uint32_t)ls[7] << 16));
}

// ============================ GEMM: C[npad,512] = Xv[npad,768] @ Bv[768,512]^T =========
// Virtual K chunks: 0-3 Xhi·Bhi, 4-7 Xlo·Bhi, 8-11 Xhi·Blo.
// hn gate (d0==384): B rows exactly 0 for k<128 → only chunks {2,3,6,7,10,11}.
// 3-stage cp.async pipeline, one barrier per stage. C stored as fp16 (halved traffic).
#define STAGE_BYTES 32768
#define GEMM_SMEM (3 * STAGE_BYTES)

__global__ __launch_bounds__(256, 2) void gemm_kernel(int npad) {
    extern __shared__ char smc[];
    uint32_t sbase = smem_u32(smc);
    int tid = threadIdx.x, lane = tid & 31, w = tid >> 5;
    int n0 = blockIdx.x * 128;
    int d0 = blockIdx.y * 128;
    int wm = w & 3, wn = w >> 2;
    int m0 = wm * 32, nw0 = wn * 64;

    const int map3[6] = {2, 3, 6, 7, 10, 11};
    bool is_hn = (d0 == 384);
    int nch = is_hn ? 6 : 12;

    float acc[2][8][4];
    #pragma unroll
    for (int a = 0; a < 2; a++)
        #pragma unroll
        for (int b = 0; b < 8; b++)
            #pragma unroll
            for (int c = 0; c < 4; c++) acc[a][b][c] = 0.f;

    auto load_chunk = [&](int c, int st) {
        const __nv_bfloat16* X = (c >= 4 && c < 8) ? g_Xlo : g_Xhi;
        const __nv_bfloat16* Asrc = X + (size_t)n0 * 256 + (c & 3) * 64;
        const __nv_bfloat16* Bsrc = g_B + (size_t)d0 * 768 + c * 64;
        uint32_t abase = sbase + st * STAGE_BYTES;
        uint32_t bbase = abase + 16384;
        #pragma unroll
        for (int i = 0; i < 4; i++) {
            int e = i * 256 + tid;
            int row = e >> 3, ch = e & 7;
            cp_async16(abase + (row * 8 + (ch ^ (row & 7))) * 16,
                       Asrc + (size_t)row * 256 + ch * 8);
        }
        #pragma unroll
        for (int i = 0; i < 4; i++) {
            int e = i * 256 + tid;
            int row = e >> 3, ch = e & 7;
            cp_async16(bbase + (row * 8 + (ch ^ (row & 7))) * 16,
                       Bsrc + (size_t)row * 768 + ch * 8);
        }
        asm volatile("cp.async.commit_group;" ::: "memory");
    };

    auto chunk_of = [&](int i) { return is_hn ? map3[i] : i; };

    load_chunk(chunk_of(0), 0);
    load_chunk(chunk_of(1), 1);

    for (int i = 0; i < nch; i++) {
        int st = i % 3;
        if (i < nch - 1) asm volatile("cp.async.wait_group 1;" ::: "memory");
        else             asm volatile("cp.async.wait_group 0;" ::: "memory");
        __syncthreads();
        // safe: barrier above proves all warps finished reading stage (i+2)%3.
        if (i + 2 < nch) load_chunk(chunk_of(i + 2), (i + 2) % 3);
        uint32_t abase = sbase + st * STAGE_BYTES;
        uint32_t bbase = abase + 16384;
        #pragma unroll
        for (int k16 = 0; k16 < 4; k16++) {
            uint32_t af[2][4], bf[4][4];
            #pragma unroll
            for (int mi = 0; mi < 2; mi++) {
                int row = m0 + mi * 16 + (lane & 15);
                int ch = k16 * 2 + (lane >> 4);
                ldm_x4(af[mi], abase + (row * 8 + (ch ^ (row & 7))) * 16);
            }
            #pragma unroll
            for (int j = 0; j < 4; j++) {
                int row = nw0 + j * 16 + (lane & 15);
                int ch = k16 * 2 + (lane >> 4);
                ldm_x4(bf[j], bbase + (row * 8 + (ch ^ (row & 7))) * 16);
            }
            #pragma unroll
            for (int mi = 0; mi < 2; mi++)
                #pragma unroll
                for (int j = 0; j < 4; j++) {
                    mma_bf16(acc[mi][2 * j],     af[mi], bf[j][0], bf[j][2]);
                    mma_bf16(acc[mi][2 * j + 1], af[mi], bf[j][1], bf[j][3]);
                }
        }
    }

    int tr = lane >> 2, tc = (lane & 3) * 2;
    #pragma unroll
    for (int mi = 0; mi < 2; mi++) {
        #pragma unroll
        for (int j = 0; j < 8; j++) {
            int node = n0 + m0 + mi * 16 + tr;
            int d = d0 + nw0 + j * 8 + tc;
            float* cp = acc[mi][j];
            *reinterpret_cast<__half2*>(g_C + (size_t)node * 512 + d) =
                __floats2half2_rn(cp[0], cp[1]);
            *reinterpret_cast<__half2*>(g_C + (size_t)(node + 8) * 512 + d) =
                __floats2half2_rn(cp[2], cp[3]);
        }
    }
}

// ============================ epilogue: gates + relu + row norm ============================
__global__ __launch_bounds__(256) void epilogue_kernel(const float* __restrict__ erb,
                                                       float* __restrict__ out, int N) {
    int gw = (int)((blockIdx.x * (size_t)blockDim.x + threadIdx.x) >> 5);
    int lane = threadIdx.x & 31;
    if (gw >= N) return;
    const uint2* C2 = reinterpret_cast<const uint2*>(g_C + (size_t)gw * 512);
    float rr[4], zz[4], xx[4], hh[4];
    ld4h(rr, C2 + lane);          // gate r: halves [lane*4 .. lane*4+3]
    ld4h(zz, C2 + 32 + lane);     // gate z
    ld4h(xx, C2 + 64 + lane);     // gate xn
    ld4h(hh, C2 + 96 + lane);     // gate hn
    float4 e4 = __ldg(reinterpret_cast<const float4*>(erb) + (size_t)gw * 32 + lane);
    const float* ee = &e4.x;
    float hv[4];
    float ss = 0.f;
    #pragma unroll
    for (int i = 0; i < 4; i++) {
        int d = lane * 4 + i;
        float r = sigmoidf_(rr[i] + __ldg(g_bias + d));
        float z = sigmoidf_(zz[i] + __ldg(g_bias + 128 + d));
        float nn = tanhf(xx[i] + __ldg(g_bias + 256 + d) + r * (hh[i] + __ldg(g_bias + 384 + d)));
        float h = fmaxf((1.f - z) * nn + z * ee[i], 0.f);
        ss += h * h;
        hv[i] = h;
    }
    #pragma unroll
    for (int o = 16; o; o >>= 1) ss += __shfl_xor_sync(0xFFFFFFFFu, ss, o);
    float inv = 1.f / fmaxf(sqrtf(ss), 1e-12f);
    reinterpret_cast<float4*>(out)[(size_t)gw * 32 + lane] =
        make_float4(hv[0] * inv, hv[1] * inv, hv[2] * inv, hv[3] * inv);
}

// ============================ launch ============================
extern "C" void kernel_launch(void* const* d_in, const int* in_sizes, int n_in,
                              void* d_out, int out_size) {
    const float* ent   = (const float*)d_in[0];
    const float* erb   = (const float*)d_in[2];
    const float* onorm = (const float*)d_in[3];
    const float* Wn    = (const float*)d_in[4];
    const float* w_ih  = (const float*)d_in[5];
    const float* w_hh  = (const float*)d_in[6];
    const float* b_ih  = (const float*)d_in[7];
    const float* b_hh  = (const float*)d_in[8];
    const int* node_id = (const int*)d_in[9];
    const int* esrc    = (const int*)d_in[10];
    const int* edst    = (const int*)d_in[11];
    int N = in_sizes[3];
    int E = in_sizes[10];
    float* out = (float*)d_out;
    int npad = ((N + 127) / 128) * 128;
    if (npad > NPAD_MAX) npad = NPAD_MAX;

    cudaFuncSetAttribute(gemm_kernel, cudaFuncAttributeMaxDynamicSharedMemorySize, GEMM_SMEM);

    prep_kernel<<<513, 256>>>(Wn, w_ih, w_hh, b_ih, b_hh);
    zero_kernel<<<512, 256>>>(N);
    int warps_needed = (E + 3) / 4;
    scatter_kernel<<<(warps_needed + 7) / 8, 256>>>(ent, node_id, esrc, edst, E);
    build_x_kernel<<<(npad * 32 + 255) / 256, 256>>>(erb, onorm, N, npad);
    dim3 ggrid(npad / 128, 4);
    gemm_kernel<<<ggrid, 256, GEMM_SMEM>>>(npad);
    epilogue_kernel<<<(N * 32 + 255) / 256, 256>>>(erb, out, N);
}